// round 16
// baseline (speedup 1.0000x reference)
#include <cuda_runtime.h>
#include <math.h>
#include <stdint.h>

// ---------------- problem constants ----------------
#define NN      16384
#define NNODE   1024
#define BBATCH  16
#define CC      16
#define HIDDIM  128
#define NHEADS  4
#define FDIM    512
#define ELOW    131072
#define ETLOW   (ELOW + NN)
#define NHIGH   256
#define EHIGH   4096
#define NEGSLOPE 0.2f
#define CAP     64
#define HFCH    16          // hf_stage1 chunks per graph (64 nodes each)

// converted-weight arena offsets (floats)
#define OBS_OFF   0
#define EMBW_OFF  524288
#define LOWWL_OFF 528384
#define LOWWR_OFF 659456
#define HIGHWL_OFF 790528
#define HIGHWR_OFF 921600
#define MLPW1_OFF 1052672
#define MLPW2_OFF 1118208
#define WTOTAL    1183744

// ---------------- scratch ----------------
__device__ float g_h    [NN * HIDDIM];
__device__ float g_hc   [NN * HIDDIM];
__device__ float g_hh   [NN * HIDDIM];
__device__ float g_xl   [NN * FDIM];
__device__ float g_xr   [NN * FDIM];
__device__ float g_s    [NN * CC];
__device__ float g_Hf   [NHIGH * HIDDIM];
__device__ float g_x    [NN * HIDDIM];
__device__ float g_xc   [NN * HIDDIM];
__device__ float g_wc   [WTOTAL];
__device__ int   g_deg  [NN];
__device__ int   g_cols [NN * CAP];
__device__ float g_hfpart [BBATCH * HFCH * CC * HIDDIM];
__device__ float g_cntpart[BBATCH * HFCH * CC];

// ---------------- tf32 helpers ----------------
__device__ __forceinline__ uint32_t tf32u(float x)
{
    uint32_t u;
    asm("cvt.rna.tf32.f32 %0, %1;" : "=r"(u) : "f"(x));
    return u;
}
__device__ __forceinline__ float tf32f(float x) { return __uint_as_float(tf32u(x)); }

#define MMA_TF32(d, a, b)                                                         \
    asm volatile(                                                                 \
        "mma.sync.aligned.m16n8k8.row.col.f32.tf32.tf32.f32 "                     \
        "{%0,%1,%2,%3}, {%4,%5,%6,%7}, {%8,%9}, {%0,%1,%2,%3};\n"                 \
        : "+f"(d[0]), "+f"(d[1]), "+f"(d[2]), "+f"(d[3])                          \
        : "r"(a[0]), "r"(a[1]), "r"(a[2]), "r"(a[3]), "r"(b[0]), "r"(b[1]))

__device__ __forceinline__ uint32_t smem_u32(const void* p)
{
    return (uint32_t)__cvta_generic_to_shared(p);
}
#define CPA16(dst, src) asm volatile("cp.async.cg.shared.global [%0], [%1], 16;" :: "r"(dst), "l"(src))
#define CPCOMMIT()      asm volatile("cp.async.commit_group;")
#define CPWAIT1()       asm volatile("cp.async.wait_group 1;")
#define CPWAIT0()       asm volatile("cp.async.wait_group 0;")

// ---------------- 128x64-tile GEMM core ----------------
__device__ __forceinline__ void gemm64_core(
    const float* __restrict__ A, const float* __restrict__ B,
    const float* __restrict__ bias, float* __restrict__ C,
    float* __restrict__ C2, float* __restrict__ Cc, const float* __restrict__ res,
    int N, int K, int mode, int row0, int col0,
    float (*As)[128][20], float (*Bs)[16][72])
{
    const int tid = threadIdx.x;
    const int lane = tid & 31;
    const int warp = tid >> 5;

    const int ar = tid >> 2;
    const int ac = (tid & 3) * 4;
    const int br = tid >> 3;
    const int bc = (tid & 7) * 8;

    float acc[2][8][4];
#pragma unroll
    for (int m = 0; m < 2; m++)
#pragma unroll
        for (int n = 0; n < 8; n++)
#pragma unroll
            for (int q = 0; q < 4; q++) acc[m][n][q] = 0.f;

    const int gq = lane >> 2;
    const int tg = lane & 3;
    const int nt = K / 16;

    auto issue = [&](int i, int buf) {
#pragma unroll
        for (int rr = 0; rr < 4; rr++)
            CPA16(smem_u32(&As[buf][ar + 32 * rr][ac]),
                  &A[(size_t)(row0 + ar + 32 * rr) * K + i * 16 + ac]);
        CPA16(smem_u32(&Bs[buf][br][bc]),     &B[(size_t)(i * 16 + br) * N + col0 + bc]);
        CPA16(smem_u32(&Bs[buf][br][bc + 4]), &B[(size_t)(i * 16 + br) * N + col0 + bc + 4]);
        CPCOMMIT();
    };

    issue(0, 0);
    if (nt > 1) issue(1, 1);
    for (int i = 0; i < nt; i++) {
        int buf = i % 3;
        if (i + 1 < nt) CPWAIT1(); else CPWAIT0();
        __syncthreads();
        if (i + 2 < nt) issue(i + 2, (i + 2) % 3);

#pragma unroll
        for (int ks = 0; ks < 2; ks++) {
            const int kb = ks * 8;
            uint32_t afr[2][4];
#pragma unroll
            for (int m = 0; m < 2; m++) {
                int r = warp * 32 + m * 16 + gq;
                int c = kb + tg;
                afr[m][0] = __float_as_uint(As[buf][r][c]);
                afr[m][1] = __float_as_uint(As[buf][r + 8][c]);
                afr[m][2] = __float_as_uint(As[buf][r][c + 4]);
                afr[m][3] = __float_as_uint(As[buf][r + 8][c + 4]);
            }
            uint32_t bfr[8][2];
#pragma unroll
            for (int n = 0; n < 8; n++) {
                int cn = n * 8 + gq;
                bfr[n][0] = __float_as_uint(Bs[buf][kb + tg][cn]);
                bfr[n][1] = __float_as_uint(Bs[buf][kb + tg + 4][cn]);
            }
#pragma unroll
            for (int m = 0; m < 2; m++)
#pragma unroll
                for (int n = 0; n < 8; n++) MMA_TF32(acc[m][n], afr[m], bfr[n]);
        }
    }

    __syncthreads();
#pragma unroll
    for (int m = 0; m < 2; m++) {
        int rbase = row0 + warp * 32 + m * 16 + gq;
#pragma unroll
        for (int n = 0; n < 8; n++) {
            int cb = col0 + n * 8 + tg * 2;
            float b0 = bias[cb], b1 = bias[cb + 1];
#pragma unroll
            for (int rr = 0; rr < 2; rr++) {
                int r = rbase + rr * 8;
                float v0 = acc[m][n][rr * 2 + 0] + b0;
                float v1 = acc[m][n][rr * 2 + 1] + b1;
                if (mode & 1) { v0 = tanhf(v0); v1 = tanhf(v1); }
                size_t off = (size_t)r * N + cb;
                if (res) { v0 += res[off]; v1 += res[off + 1]; }
                if (mode & 2) { v0 = tf32f(v0); v1 = tf32f(v1); }
                float2 vv = make_float2(v0, v1);
                *(float2*)&C[off] = vv;
                if (C2) *(float2*)&C2[off] = vv;
                if (Cc) *(float2*)&Cc[off] = make_float2(tf32f(v0), tf32f(v1));
            }
        }
    }
}

__global__ __launch_bounds__(128) void gemm64_kernel(
    const float* __restrict__ A, const float* __restrict__ B,
    const float* __restrict__ bias, float* __restrict__ C,
    float* __restrict__ C2, float* __restrict__ Cc, const float* __restrict__ res,
    int N, int K, int mode)
{
    __shared__ __align__(16) float As[3][128][20];
    __shared__ __align__(16) float Bs[3][16][72];
    gemm64_core(A, B, bias, C, C2, Cc, res, N, K, mode,
                blockIdx.y * 128, blockIdx.x * 64, As, Bs);
}

__global__ __launch_bounds__(128) void dual_gemm64_kernel(
    const float* __restrict__ A,
    const float* __restrict__ B1, const float* __restrict__ bias1, float* __restrict__ C1,
    const float* __restrict__ B2, const float* __restrict__ bias2, float* __restrict__ C2o,
    int K)
{
    __shared__ __align__(16) float As[3][128][20];
    __shared__ __align__(16) float Bs[3][16][72];
    int col0 = (blockIdx.x & 7) * 64;
    if (blockIdx.x < 8)
        gemm64_core(A, B1, bias1, C1, nullptr, nullptr, nullptr, FDIM, K, 0,
                    blockIdx.y * 128, col0, As, Bs);
    else
        gemm64_core(A, B2, bias2, C2o, nullptr, nullptr, nullptr, FDIM, K, 0,
                    blockIdx.y * 128, col0, As, Bs);
}

// ---------------- weight/obs conversion + adjacency init ----------------
__global__ void cvt_init(
    const float* __restrict__ obs, const float* __restrict__ embW,
    const float* __restrict__ lowWl, const float* __restrict__ lowWr,
    const float* __restrict__ highWl, const float* __restrict__ highWr,
    const float* __restrict__ W1, const float* __restrict__ W2)
{
    int i = blockIdx.x * blockDim.x + threadIdx.x;
    if (i < NN) g_deg[i] = 0;
    int stride = gridDim.x * blockDim.x;
    for (int idx = i; idx < WTOTAL; idx += stride) {
        float v;
        if (idx < EMBW_OFF)        v = obs[idx - OBS_OFF];
        else if (idx < LOWWL_OFF)  v = embW[idx - EMBW_OFF];
        else if (idx < LOWWR_OFF)  v = lowWl[idx - LOWWL_OFF];
        else if (idx < HIGHWL_OFF) v = lowWr[idx - LOWWR_OFF];
        else if (idx < HIGHWR_OFF) v = highWl[idx - HIGHWL_OFF];
        else if (idx < MLPW1_OFF)  v = highWr[idx - HIGHWR_OFF];
        else if (idx < MLPW2_OFF)  v = W1[idx - MLPW1_OFF];
        else                       v = W2[idx - MLPW2_OFF];
        g_wc[idx] = tf32f(v);
    }
}

// ---------------- adjacency ----------------
__global__ void csr_scatter(const int* __restrict__ edge_index)
{
    int i = blockIdx.x * blockDim.x + threadIdx.x;
    if (i >= ETLOW) return;
    int s, d;
    if (i < ELOW) { s = edge_index[i]; d = edge_index[ELOW + i]; }
    else { s = d = i - ELOW; }
    int slot = atomicAdd(&g_deg[d], 1);
    if (slot < CAP) g_cols[d * CAP + slot] = s;
}

// ---------------- fused GAT layer (low level; in-block sort option) ----------------
__global__ __launch_bounds__(128) void fused_gat(
    const float* __restrict__ xl, const float* __restrict__ xr,
    const int* __restrict__ deg, int* __restrict__ cols, int cap,
    const float* __restrict__ att,
    float* __restrict__ h, float* __restrict__ hc,
    const float* __restrict__ bias, const float* __restrict__ g,
    const float* __restrict__ beta, const float* __restrict__ res,
    int do_silu, int do_sort)
{
    int row = blockIdx.x;
    int t = threadIdx.x;
    int w = t >> 5, lane = t & 31;
    int d0 = w * HIDDIM + lane * 4;

    float4 xr4 = *(const float4*)&xr[(size_t)row * FDIM + d0];
    float4 at4 = *(const float4*)&att[d0];
    int* c = &cols[(size_t)row * cap];
    int n = min(deg[row], cap);

    __shared__ int sc[CAP];
    if (w == 0) {
        int v0 = (lane < n)      ? c[lane]      : 0x7fffffff;
        int v1 = (lane + 32 < n) ? c[lane + 32] : 0x7fffffff;
        if (do_sort) {
            int r0 = 0, r1 = 0;
            for (int j = 0; j < n; j++) {
                int vj = __shfl_sync(0xffffffffu, (j < 32) ? v0 : v1, j & 31);
                r0 += (vj < v0) | ((vj == v0) & (j < lane));
                r1 += (vj < v1) | ((vj == v1) & (j < lane + 32));
            }
            __syncwarp();
            if (lane < n)      { sc[r0] = v0; c[r0] = v0; }
            if (lane + 32 < n) { sc[r1] = v1; c[r1] = v1; }
        } else {
            if (lane < n)      sc[lane] = v0;
            if (lane + 32 < n) sc[lane + 32] = v1;
        }
    }
    __syncthreads();

    float z = 0.f;
    float a0 = 0.f, a1 = 0.f, a2 = 0.f, a3 = 0.f;

    float4 x0 = *(const float4*)&xl[(size_t)sc[0] * FDIM + d0];
    float4 x1 = (n > 1) ? *(const float4*)&xl[(size_t)sc[1] * FDIM + d0] : x0;

    for (int e = 0; e < n; e += 2) {
        float4 xn0 = x0, xn1 = x1;
        if (e + 2 < n) xn0 = *(const float4*)&xl[(size_t)sc[e + 2] * FDIM + d0];
        if (e + 3 < n) xn1 = *(const float4*)&xl[(size_t)sc[e + 3] * FDIM + d0];

        float u0, u1, u2, u3;
        u0 = x0.x + xr4.x; u0 = u0 > 0.f ? u0 : NEGSLOPE * u0;
        u1 = x0.y + xr4.y; u1 = u1 > 0.f ? u1 : NEGSLOPE * u1;
        u2 = x0.z + xr4.z; u2 = u2 > 0.f ? u2 : NEGSLOPE * u2;
        u3 = x0.w + xr4.w; u3 = u3 > 0.f ? u3 : NEGSLOPE * u3;
        float da = u0 * at4.x + u1 * at4.y + u2 * at4.z + u3 * at4.w;

        u0 = x1.x + xr4.x; u0 = u0 > 0.f ? u0 : NEGSLOPE * u0;
        u1 = x1.y + xr4.y; u1 = u1 > 0.f ? u1 : NEGSLOPE * u1;
        u2 = x1.z + xr4.z; u2 = u2 > 0.f ? u2 : NEGSLOPE * u2;
        u3 = x1.w + xr4.w; u3 = u3 > 0.f ? u3 : NEGSLOPE * u3;
        float db = u0 * at4.x + u1 * at4.y + u2 * at4.z + u3 * at4.w;

#pragma unroll
        for (int o = 16; o; o >>= 1) {
            da += __shfl_xor_sync(0xffffffffu, da, o);
            db += __shfl_xor_sync(0xffffffffu, db, o);
        }
        float pa = __expf(da);
        float pb = (e + 1 < n) ? __expf(db) : 0.f;
        z += pa + pb;
        a0 += pa * x0.x + pb * x1.x;
        a1 += pa * x0.y + pb * x1.y;
        a2 += pa * x0.z + pb * x1.z;
        a3 += pa * x0.w + pb * x1.w;
        x0 = xn0;
        x1 = xn1;
    }

    __shared__ __align__(16) float sh[4][HIDDIM];
    float inv = 0.25f / z;
    ((float4*)sh[w])[lane] = make_float4(a0 * inv, a1 * inv, a2 * inv, a3 * inv);
    __syncthreads();

    float v = sh[0][t] + sh[1][t] + sh[2][t] + sh[3][t] + bias[t];

    __shared__ float red[4];
    float sum = v;
#pragma unroll
    for (int o = 16; o; o >>= 1) sum += __shfl_xor_sync(0xffffffffu, sum, o);
    if (lane == 0) red[w] = sum;
    __syncthreads();
    float mu = (red[0] + red[1] + red[2] + red[3]) * (1.f / 128.f);
    __syncthreads();
    float dv = v - mu;
    float sq = dv * dv;
#pragma unroll
    for (int o = 16; o; o >>= 1) sq += __shfl_xor_sync(0xffffffffu, sq, o);
    if (lane == 0) red[w] = sq;
    __syncthreads();
    float var = (red[0] + red[1] + red[2] + red[3]) * (1.f / 128.f);
    float y = dv * rsqrtf(var + 1e-5f) * g[t] + beta[t];
    if (do_silu) y = y / (1.f + expf(-y));
    y += h[(size_t)row * HIDDIM + t];
    if (res) y += res[(size_t)row * HIDDIM + t];
    h[(size_t)row * HIDDIM + t] = y;
    if (hc) hc[(size_t)row * HIDDIM + t] = tf32f(y);
}

// ---------------- cluster features + fused pooling softmax ----------------
__global__ __launch_bounds__(128) void hf_stage1(const float* __restrict__ h,
                                                 const float* __restrict__ poolW,
                                                 const float* __restrict__ poolB)
{
    int b = blockIdx.x >> 4, chunk = blockIdx.x & 15;
    int t = threadIdx.x;
    int w = t >> 5, lane = t & 31;
    __shared__ float hs[64][HIDDIM + 1];
    __shared__ float ss[64][CC + 1];
    __shared__ float pw[HIDDIM * CC];
    int n0 = chunk * 64;
    const float* hp0 = h + ((size_t)(b * NNODE + n0)) * HIDDIM;
    for (int n = 0; n < 64; n++)
        hs[n][t] = hp0[(size_t)n * HIDDIM + t];
    for (int i = t; i < HIDDIM * CC; i += 128) pw[i] = poolW[i];
    __syncthreads();

    {
        int cidx = lane & 15;
        float pb = poolB[cidx];
#pragma unroll
        for (int pr = 0; pr < 8; pr++) {
            int node = w * 16 + pr * 2 + (lane >> 4);
            float a = 0.f;
#pragma unroll 8
            for (int d = 0; d < HIDDIM; d++) a += hs[node][d] * pw[d * CC + cidx];
            a += pb;
            float mx = a;
#pragma unroll
            for (int o = 8; o; o >>= 1) mx = fmaxf(mx, __shfl_xor_sync(0xffffffffu, mx, o));
            float e = __expf(a - mx);
            float zz = e;
#pragma unroll
            for (int o = 8; o; o >>= 1) zz += __shfl_xor_sync(0xffffffffu, zz, o);
            float sv = e / zz;
            ss[node][cidx] = sv;
            g_s[((size_t)(b * NNODE + n0 + node)) * CC + cidx] = sv;
        }
    }
    __syncthreads();

    float acc[CC];
#pragma unroll
    for (int c = 0; c < CC; c++) acc[c] = 0.f;
    for (int n = 0; n < 64; n++) {
        float hv = hs[n][t];
#pragma unroll
        for (int c = 0; c < CC; c++) acc[c] += ss[n][c] * hv;
    }
    size_t base = ((size_t)blockIdx.x) * CC * HIDDIM;
#pragma unroll
    for (int c = 0; c < CC; c++) g_hfpart[base + (size_t)c * HIDDIM + t] = acc[c];
    if (t < CC) {
        float cs = 0.f;
        for (int n = 0; n < 64; n++) cs += ss[n][t];
        g_cntpart[blockIdx.x * CC + t] = cs;
    }
}

// ---------------- entire high-level stack: one block per graph ----------------
// fuses hf_stage2 + (transform + attention + LN + residual) x 2 layers.
// smem: hf[16][128] | hfres[16][128] | xl[16][512] | xr[16][512] | cnts[16]
#define HS_FLOATS (2048 + 2048 + 8192 + 8192 + 16)
__global__ __launch_bounds__(256) void high_stack(
    const float* __restrict__ wc,
    const float* __restrict__ bl, const float* __restrict__ br,
    const float* __restrict__ att, const float* __restrict__ bias,
    const float* __restrict__ g, const float* __restrict__ beta,
    float* __restrict__ Hf_out)
{
    extern __shared__ float sm[];
    float* hf    = sm;
    float* hfres = sm + 2048;
    float* xls   = sm + 4096;
    float* xrs   = sm + 12288;
    float* cnts  = sm + 20480;
    int b = blockIdx.x;
    int t = threadIdx.x;
    int w = t >> 5, lane = t & 31;

    // fused hf_stage2: Hf = sum(partials)/max(cnt,1e-5)
    if (t < CC) {
        float cs = 0.f;
        for (int ch = 0; ch < HFCH; ch++) cs += g_cntpart[(b * HFCH + ch) * CC + t];
        cnts[t] = fmaxf(cs, 1e-5f);
    }
    __syncthreads();
    for (int idx = t; idx < 2048; idx += 256) {
        int c = idx >> 7, d = idx & 127;
        float acc = 0.f;
        for (int ch = 0; ch < HFCH; ch++)
            acc += g_hfpart[(((size_t)(b * HFCH + ch)) * CC + c) * HIDDIM + d];
        float v = acc / cnts[c];
        hf[idx] = v;
        hfres[idx] = v;
    }
    __syncthreads();

    for (int j = 0; j < 2; j++) {
        // transforms: threads 0..127 -> xl, 128..255 -> xr (fp32 FFMA)
        {
            int side = t >> 7;
            int tl = t & 127;
            const float* W = wc + (side ? HIGHWR_OFF : HIGHWL_OFF) + j * 65536;
            const float* bb = (side ? br : bl) + j * FDIM;
            float* dst = side ? xrs : xls;
#pragma unroll
            for (int cg = 0; cg < 4; cg++) {
                int o = tl + cg * 128;
                float acc16[16];
#pragma unroll
                for (int n = 0; n < 16; n++) acc16[n] = 0.f;
                for (int k = 0; k < 128; k++) {
                    float wv = W[k * FDIM + o];
#pragma unroll
                    for (int n = 0; n < 16; n++) acc16[n] += hf[n * 128 + k] * wv;
                }
                float bv = bb[o];
#pragma unroll
                for (int n = 0; n < 16; n++) dst[n * FDIM + o] = acc16[n] + bv;
            }
        }
        __syncthreads();

        // attention: warp w handles dst nodes w*2, w*2+1 (16 srcs fully connected)
#pragma unroll
        for (int dd = 0; dd < 2; dd++) {
            int d = w * 2 + dd;
            float ag[4] = {0.f, 0.f, 0.f, 0.f};
#pragma unroll
            for (int hd = 0; hd < NHEADS; hd++) {
                int base = hd * HIDDIM + lane * 4;
                float4 xr4 = *(float4*)&xrs[d * FDIM + base];
                float4 at4 = *(const float4*)&att[(size_t)j * FDIM + base];
                float p[16];
                float z = 0.f;
#pragma unroll
                for (int s = 0; s < 16; s++) {
                    float4 x4 = *(float4*)&xls[s * FDIM + base];
                    float u0 = x4.x + xr4.x; u0 = u0 > 0.f ? u0 : NEGSLOPE * u0;
                    float u1 = x4.y + xr4.y; u1 = u1 > 0.f ? u1 : NEGSLOPE * u1;
                    float u2 = x4.z + xr4.z; u2 = u2 > 0.f ? u2 : NEGSLOPE * u2;
                    float u3 = x4.w + xr4.w; u3 = u3 > 0.f ? u3 : NEGSLOPE * u3;
                    float dot = u0 * at4.x + u1 * at4.y + u2 * at4.z + u3 * at4.w;
#pragma unroll
                    for (int o = 16; o; o >>= 1) dot += __shfl_xor_sync(0xffffffffu, dot, o);
                    p[s] = __expf(dot);
                    z += p[s];
                }
                float inv = 1.f / z;
#pragma unroll
                for (int s = 0; s < 16; s++) {
                    float4 x4 = *(float4*)&xls[s * FDIM + base];
                    float al = p[s] * inv;
                    ag[0] += al * x4.x;
                    ag[1] += al * x4.y;
                    ag[2] += al * x4.z;
                    ag[3] += al * x4.w;
                }
            }
            // mean over heads + bias, then LN (warp-wide over 128 feats)
            int o0 = lane * 4;
            float v[4];
#pragma unroll
            for (int q = 0; q < 4; q++)
                v[q] = ag[q] * 0.25f + bias[j * HIDDIM + o0 + q];
            float sum = v[0] + v[1] + v[2] + v[3];
#pragma unroll
            for (int o = 16; o; o >>= 1) sum += __shfl_xor_sync(0xffffffffu, sum, o);
            float mu = sum * (1.f / 128.f);
            float sq = 0.f;
#pragma unroll
            for (int q = 0; q < 4; q++) { v[q] -= mu; sq += v[q] * v[q]; }
#pragma unroll
            for (int o = 16; o; o >>= 1) sq += __shfl_xor_sync(0xffffffffu, sq, o);
            float rstd = rsqrtf(sq * (1.f / 128.f) + 1e-5f);
#pragma unroll
            for (int q = 0; q < 4; q++) {
                float y = v[q] * rstd * g[j * HIDDIM + o0 + q] + beta[j * HIDDIM + o0 + q];
                if (j == 0) y = y / (1.f + expf(-y));
                y += hf[d * 128 + o0 + q];
                if (j == 1) y += hfres[d * 128 + o0 + q];
                v[q] = y;
            }
            __syncwarp();
#pragma unroll
            for (int q = 0; q < 4; q++) hf[d * 128 + o0 + q] = v[q];
        }
        __syncthreads();
    }

    for (int idx = t; idx < 2048; idx += 256)
        Hf_out[(size_t)b * 2048 + idx] = hf[idx];
}

// x = hh + s @ Hf; tf32 copy for MLP1
__global__ void unpool_kernel(const float* __restrict__ s, const float* __restrict__ Hf,
                              const float* __restrict__ hh,
                              float* __restrict__ x, float* __restrict__ xc)
{
    int idx = blockIdx.x * blockDim.x + threadIdx.x;
    if (idx >= NN * HIDDIM) return;
    int n = idx >> 7, t = idx & 127;
    int b = n >> 10;
    float v = hh[idx];
    const float* sp = s + (size_t)n * CC;
    const float* Hp = Hf + (size_t)(b * CC) * HIDDIM + t;
#pragma unroll
    for (int c = 0; c < CC; c++) v += sp[c] * Hp[(size_t)c * HIDDIM];
    x[idx] = v;
    xc[idx] = tf32f(v);
}

// ---------------- host orchestration ----------------
struct Ptrs {
    float *h, *hc, *hh, *xl, *xr, *s, *Hf, *x, *xc, *wc;
    int *deg, *cols;
};

static void get_ptrs(Ptrs& P)
{
    cudaGetSymbolAddress((void**)&P.h, g_h);
    cudaGetSymbolAddress((void**)&P.hc, g_hc);
    cudaGetSymbolAddress((void**)&P.hh, g_hh);
    cudaGetSymbolAddress((void**)&P.xl, g_xl);
    cudaGetSymbolAddress((void**)&P.xr, g_xr);
    cudaGetSymbolAddress((void**)&P.s, g_s);
    cudaGetSymbolAddress((void**)&P.Hf, g_Hf);
    cudaGetSymbolAddress((void**)&P.x, g_x);
    cudaGetSymbolAddress((void**)&P.xc, g_xc);
    cudaGetSymbolAddress((void**)&P.wc, g_wc);
    cudaGetSymbolAddress((void**)&P.deg, g_deg);
    cudaGetSymbolAddress((void**)&P.cols, g_cols);
}

extern "C" void kernel_launch(void* const* d_in, const int* in_sizes, int n_in,
                              void* d_out, int out_size)
{
    int p = 0;
    const float* obs        = (const float*)d_in[p++];
    const int*   edge_index = (const int*)d_in[p++];
    if (n_in >= 27) p++;  // skip n_node scalar if present
    const float* emb_W   = (const float*)d_in[p++];
    const float* emb_b   = (const float*)d_in[p++];
    const float* pool_W  = (const float*)d_in[p++];
    const float* pool_b  = (const float*)d_in[p++];
    const float* mlp_W1  = (const float*)d_in[p++];
    const float* mlp_b1  = (const float*)d_in[p++];
    const float* mlp_W2  = (const float*)d_in[p++];
    const float* mlp_b2  = (const float*)d_in[p++];
    const float* low_Wl   = (const float*)d_in[p++];
    const float* low_bl   = (const float*)d_in[p++];
    const float* low_Wr   = (const float*)d_in[p++];
    const float* low_br   = (const float*)d_in[p++];
    const float* low_att  = (const float*)d_in[p++];
    const float* low_bias = (const float*)d_in[p++];
    const float* low_g    = (const float*)d_in[p++];
    const float* low_beta = (const float*)d_in[p++];
    const float* high_Wl   = (const float*)d_in[p++];
    const float* high_bl   = (const float*)d_in[p++];
    const float* high_Wr   = (const float*)d_in[p++];
    const float* high_br   = (const float*)d_in[p++];
    const float* high_att  = (const float*)d_in[p++];
    const float* high_bias = (const float*)d_in[p++];
    const float* high_g    = (const float*)d_in[p++];
    const float* high_beta = (const float*)d_in[p++];

    Ptrs P;
    get_ptrs(P);
    float* out = (float*)d_out;

    static bool attr_set = false;
    if (!attr_set) {
        cudaFuncSetAttribute(high_stack, cudaFuncAttributeMaxDynamicSharedMemorySize,
                             HS_FLOATS * 4);
        attr_set = true;
    }

    // 1. weight/obs tf32 conversion + adjacency init
    cvt_init<<<1024, 256>>>(obs, emb_W, low_Wl, low_Wr, high_Wl, high_Wr,
                            mlp_W1, mlp_W2);
    // 2. embed
    gemm64_kernel<<<dim3(2, NN / 128), 128>>>(P.wc + OBS_OFF, P.wc + EMBW_OFF, emb_b,
                                              P.h, P.hh, P.hc, nullptr,
                                              HIDDIM, 32, 0);
    // 3. edge scatter
    csr_scatter<<<(ETLOW + 255) / 256, 256>>>(edge_index);
    // 4. low layer 0 transforms  <- profiled slot
    dual_gemm64_kernel<<<dim3(16, NN / 128), 128>>>(
        P.hc, P.wc + LOWWL_OFF, low_bl, P.xl,
        P.wc + LOWWR_OFF, low_br, P.xr, HIDDIM);
    // 5. low layer 0 attention (sorts adjacency in-block, writes back)
    fused_gat<<<NN, 128>>>(P.xl, P.xr, P.deg, P.cols, CAP, low_att, P.h, P.hc,
                           low_bias, low_g, low_beta, nullptr, 1, 1);
    // 6-7. low layer 1
    dual_gemm64_kernel<<<dim3(16, NN / 128), 128>>>(
        P.hc, P.wc + LOWWL_OFF + 65536, low_bl + FDIM, P.xl,
        P.wc + LOWWR_OFF + 65536, low_br + FDIM, P.xr, HIDDIM);
    fused_gat<<<NN, 128>>>(P.xl, P.xr, P.deg, P.cols, CAP, low_att + FDIM, P.h, nullptr,
                           low_bias + HIDDIM, low_g + HIDDIM, low_beta + HIDDIM,
                           P.hh, 0, 0);

    // 8. cluster features (+ fused pooling softmax)
    hf_stage1<<<BBATCH * HFCH, 128>>>(P.h, pool_W, pool_b);

    // 9. entire high-level stack (hf_stage2 + 2 GAT layers) in one launch
    high_stack<<<BBATCH, 256, HS_FLOATS * 4>>>(
        P.wc, high_bl, high_br, high_att, high_bias, high_g, high_beta, P.Hf);

    // 10. unpool + residual
    unpool_kernel<<<(NN * HIDDIM + 255) / 256, 256>>>(P.s, P.Hf, P.hh, P.x, P.xc);

    // 11-12. MLP
    gemm64_kernel<<<dim3(8, NN / 128), 128>>>(P.xc, P.wc + MLPW1_OFF, mlp_b1, P.xl,
                                              nullptr, nullptr, nullptr,
                                              FDIM, HIDDIM, 3);
    gemm64_kernel<<<dim3(2, NN / 128), 128>>>(P.xl, P.wc + MLPW2_OFF, mlp_b2, out,
                                              nullptr, nullptr, P.x,
                                              HIDDIM, FDIM, 0);
}

// round 17
// speedup vs baseline: 1.6340x; 1.6340x over previous
#include <cuda_runtime.h>
#include <math.h>
#include <stdint.h>

// ---------------- problem constants ----------------
#define NN      16384
#define NNODE   1024
#define BBATCH  16
#define CC      16
#define HIDDIM  128
#define NHEADS  4
#define FDIM    512
#define ELOW    131072
#define ETLOW   (ELOW + NN)
#define NHIGH   256
#define EHIGH   4096
#define NEGSLOPE 0.2f
#define CAP     64
#define HFCH    16          // hf_stage1 chunks per graph (64 nodes each)

// converted-weight arena offsets (floats)
#define OBS_OFF   0
#define EMBW_OFF  524288
#define LOWWL_OFF 528384
#define LOWWR_OFF 659456
#define HIGHWL_OFF 790528
#define HIGHWR_OFF 921600
#define MLPW1_OFF 1052672
#define MLPW2_OFF 1118208
#define WTOTAL    1183744

// ---------------- scratch ----------------
__device__ float g_h    [NN * HIDDIM];
__device__ float g_hc   [NN * HIDDIM];
__device__ float g_hh   [NN * HIDDIM];
__device__ float g_xl   [NN * FDIM];
__device__ float g_xr   [NN * FDIM];
__device__ float g_s    [NN * CC];
__device__ float g_Hf   [NHIGH * HIDDIM];
__device__ float g_Hfc  [NHIGH * HIDDIM];
__device__ float g_HfRes[NHIGH * HIDDIM];
__device__ float g_x    [NN * HIDDIM];
__device__ float g_xc   [NN * HIDDIM];
__device__ float g_wc   [WTOTAL];
__device__ int   g_deg  [NN];
__device__ int   g_cols [NN * CAP];
__device__ int   g_hdeg [NHIGH];
__device__ int   g_hcols[EHIGH];
__device__ float g_hfpart [BBATCH * HFCH * CC * HIDDIM];
__device__ float g_cntpart[BBATCH * HFCH * CC];

// ---------------- tf32 helpers ----------------
__device__ __forceinline__ uint32_t tf32u(float x)
{
    uint32_t u;
    asm("cvt.rna.tf32.f32 %0, %1;" : "=r"(u) : "f"(x));
    return u;
}
__device__ __forceinline__ float tf32f(float x) { return __uint_as_float(tf32u(x)); }

#define MMA_TF32(d, a, b)                                                         \
    asm volatile(                                                                 \
        "mma.sync.aligned.m16n8k8.row.col.f32.tf32.tf32.f32 "                     \
        "{%0,%1,%2,%3}, {%4,%5,%6,%7}, {%8,%9}, {%0,%1,%2,%3};\n"                 \
        : "+f"(d[0]), "+f"(d[1]), "+f"(d[2]), "+f"(d[3])                          \
        : "r"(a[0]), "r"(a[1]), "r"(a[2]), "r"(a[3]), "r"(b[0]), "r"(b[1]))

__device__ __forceinline__ uint32_t smem_u32(const void* p)
{
    return (uint32_t)__cvta_generic_to_shared(p);
}
#define CPA16(dst, src) asm volatile("cp.async.cg.shared.global [%0], [%1], 16;" :: "r"(dst), "l"(src))
#define CPCOMMIT()      asm volatile("cp.async.commit_group;")
#define CPWAIT1()       asm volatile("cp.async.wait_group 1;")
#define CPWAIT0()       asm volatile("cp.async.wait_group 0;")

// ---------------- 128x64-tile GEMM core (128 threads) ----------------
__device__ __forceinline__ void gemm64_core(
    const float* __restrict__ A, const float* __restrict__ B,
    const float* __restrict__ bias, float* __restrict__ C,
    float* __restrict__ C2, float* __restrict__ Cc, const float* __restrict__ res,
    int N, int K, int mode, int row0, int col0,
    float (*As)[128][20], float (*Bs)[16][72])
{
    const int tid = threadIdx.x;
    const int lane = tid & 31;
    const int warp = tid >> 5;

    const int ar = tid >> 2;
    const int ac = (tid & 3) * 4;
    const int br = tid >> 3;
    const int bc = (tid & 7) * 8;

    float acc[2][8][4];
#pragma unroll
    for (int m = 0; m < 2; m++)
#pragma unroll
        for (int n = 0; n < 8; n++)
#pragma unroll
            for (int q = 0; q < 4; q++) acc[m][n][q] = 0.f;

    const int gq = lane >> 2;
    const int tg = lane & 3;
    const int nt = K / 16;

    auto issue = [&](int i, int buf) {
#pragma unroll
        for (int rr = 0; rr < 4; rr++)
            CPA16(smem_u32(&As[buf][ar + 32 * rr][ac]),
                  &A[(size_t)(row0 + ar + 32 * rr) * K + i * 16 + ac]);
        CPA16(smem_u32(&Bs[buf][br][bc]),     &B[(size_t)(i * 16 + br) * N + col0 + bc]);
        CPA16(smem_u32(&Bs[buf][br][bc + 4]), &B[(size_t)(i * 16 + br) * N + col0 + bc + 4]);
        CPCOMMIT();
    };

    issue(0, 0);
    if (nt > 1) issue(1, 1);
    for (int i = 0; i < nt; i++) {
        int buf = i % 3;
        if (i + 1 < nt) CPWAIT1(); else CPWAIT0();
        __syncthreads();
        if (i + 2 < nt) issue(i + 2, (i + 2) % 3);

#pragma unroll
        for (int ks = 0; ks < 2; ks++) {
            const int kb = ks * 8;
            uint32_t afr[2][4];
#pragma unroll
            for (int m = 0; m < 2; m++) {
                int r = warp * 32 + m * 16 + gq;
                int c = kb + tg;
                afr[m][0] = __float_as_uint(As[buf][r][c]);
                afr[m][1] = __float_as_uint(As[buf][r + 8][c]);
                afr[m][2] = __float_as_uint(As[buf][r][c + 4]);
                afr[m][3] = __float_as_uint(As[buf][r + 8][c + 4]);
            }
            uint32_t bfr[8][2];
#pragma unroll
            for (int n = 0; n < 8; n++) {
                int cn = n * 8 + gq;
                bfr[n][0] = __float_as_uint(Bs[buf][kb + tg][cn]);
                bfr[n][1] = __float_as_uint(Bs[buf][kb + tg + 4][cn]);
            }
#pragma unroll
            for (int m = 0; m < 2; m++)
#pragma unroll
                for (int n = 0; n < 8; n++) MMA_TF32(acc[m][n], afr[m], bfr[n]);
        }
    }

    __syncthreads();
#pragma unroll
    for (int m = 0; m < 2; m++) {
        int rbase = row0 + warp * 32 + m * 16 + gq;
#pragma unroll
        for (int n = 0; n < 8; n++) {
            int cb = col0 + n * 8 + tg * 2;
            float b0 = bias[cb], b1 = bias[cb + 1];
#pragma unroll
            for (int rr = 0; rr < 2; rr++) {
                int r = rbase + rr * 8;
                float v0 = acc[m][n][rr * 2 + 0] + b0;
                float v1 = acc[m][n][rr * 2 + 1] + b1;
                if (mode & 1) { v0 = tanhf(v0); v1 = tanhf(v1); }
                size_t off = (size_t)r * N + cb;
                if (res) { v0 += res[off]; v1 += res[off + 1]; }
                if (mode & 2) { v0 = tf32f(v0); v1 = tf32f(v1); }
                float2 vv = make_float2(v0, v1);
                *(float2*)&C[off] = vv;
                if (C2) *(float2*)&C2[off] = vv;
                if (Cc) *(float2*)&Cc[off] = make_float2(tf32f(v0), tf32f(v1));
            }
        }
    }
}

__global__ __launch_bounds__(128) void gemm64_kernel(
    const float* __restrict__ A, const float* __restrict__ B,
    const float* __restrict__ bias, float* __restrict__ C,
    float* __restrict__ C2, float* __restrict__ Cc, const float* __restrict__ res,
    int N, int K, int mode)
{
    __shared__ __align__(16) float As[3][128][20];
    __shared__ __align__(16) float Bs[3][16][72];
    gemm64_core(A, B, bias, C, C2, Cc, res, N, K, mode,
                blockIdx.y * 128, blockIdx.x * 64, As, Bs);
}

__global__ __launch_bounds__(128) void dual_gemm64_kernel(
    const float* __restrict__ A,
    const float* __restrict__ B1, const float* __restrict__ bias1, float* __restrict__ C1,
    const float* __restrict__ B2, const float* __restrict__ bias2, float* __restrict__ C2o,
    int K)
{
    __shared__ __align__(16) float As[3][128][20];
    __shared__ __align__(16) float Bs[3][16][72];
    int col0 = (blockIdx.x & 7) * 64;
    if (blockIdx.x < 8)
        gemm64_core(A, B1, bias1, C1, nullptr, nullptr, nullptr, FDIM, K, 0,
                    blockIdx.y * 128, col0, As, Bs);
    else
        gemm64_core(A, B2, bias2, C2o, nullptr, nullptr, nullptr, FDIM, K, 0,
                    blockIdx.y * 128, col0, As, Bs);
}

// ---------------- 128x128-tile GEMM (256 threads) — better A reuse (MLP1) ----------------
__global__ __launch_bounds__(256) void tgemm128_kernel(
    const float* __restrict__ A, const float* __restrict__ B,
    const float* __restrict__ bias, float* __restrict__ C,
    int N, int K, int mode)
{
    __shared__ __align__(16) float As[3][128][20];
    __shared__ __align__(16) float Bs[3][16][136];

    const int tid = threadIdx.x;
    const int lane = tid & 31;
    const int warp = tid >> 5;
    const int wr = warp >> 1;
    const int wc = warp & 1;
    const int row0 = blockIdx.y * 128;
    const int col0 = blockIdx.x * 128;

    const int ar = tid >> 2;
    const int ac = (tid & 3) * 4;
    const int br = tid >> 4;
    const int bc = (tid & 15) * 8;

    float acc[2][8][4];
#pragma unroll
    for (int m = 0; m < 2; m++)
#pragma unroll
        for (int n = 0; n < 8; n++)
#pragma unroll
            for (int q = 0; q < 4; q++) acc[m][n][q] = 0.f;

    const int gq = lane >> 2;
    const int tg = lane & 3;
    const int nt = K / 16;

    auto issue = [&](int i, int buf) {
        CPA16(smem_u32(&As[buf][ar][ac]),      &A[(size_t)(row0 + ar) * K + i * 16 + ac]);
        CPA16(smem_u32(&As[buf][ar + 64][ac]), &A[(size_t)(row0 + ar + 64) * K + i * 16 + ac]);
        CPA16(smem_u32(&Bs[buf][br][bc]),      &B[(size_t)(i * 16 + br) * N + col0 + bc]);
        CPA16(smem_u32(&Bs[buf][br][bc + 4]),  &B[(size_t)(i * 16 + br) * N + col0 + bc + 4]);
        CPCOMMIT();
    };

    issue(0, 0);
    if (nt > 1) issue(1, 1);
    for (int i = 0; i < nt; i++) {
        int buf = i % 3;
        if (i + 1 < nt) CPWAIT1(); else CPWAIT0();
        __syncthreads();
        if (i + 2 < nt) issue(i + 2, (i + 2) % 3);

#pragma unroll
        for (int ks = 0; ks < 2; ks++) {
            const int kb = ks * 8;
            uint32_t afr[2][4];
#pragma unroll
            for (int m = 0; m < 2; m++) {
                int r = wr * 32 + m * 16 + gq;
                int c = kb + tg;
                afr[m][0] = __float_as_uint(As[buf][r][c]);
                afr[m][1] = __float_as_uint(As[buf][r + 8][c]);
                afr[m][2] = __float_as_uint(As[buf][r][c + 4]);
                afr[m][3] = __float_as_uint(As[buf][r + 8][c + 4]);
            }
            uint32_t bfr[8][2];
#pragma unroll
            for (int n = 0; n < 8; n++) {
                int cn = wc * 64 + n * 8 + gq;
                bfr[n][0] = __float_as_uint(Bs[buf][kb + tg][cn]);
                bfr[n][1] = __float_as_uint(Bs[buf][kb + tg + 4][cn]);
            }
#pragma unroll
            for (int m = 0; m < 2; m++)
#pragma unroll
                for (int n = 0; n < 8; n++) MMA_TF32(acc[m][n], afr[m], bfr[n]);
        }
    }

    __syncthreads();
#pragma unroll
    for (int m = 0; m < 2; m++) {
        int rbase = row0 + wr * 32 + m * 16 + gq;
#pragma unroll
        for (int n = 0; n < 8; n++) {
            int cb = col0 + wc * 64 + n * 8 + tg * 2;
            float b0 = bias[cb], b1 = bias[cb + 1];
#pragma unroll
            for (int rr = 0; rr < 2; rr++) {
                int r = rbase + rr * 8;
                float v0 = acc[m][n][rr * 2 + 0] + b0;
                float v1 = acc[m][n][rr * 2 + 1] + b1;
                if (mode & 1) { v0 = tanhf(v0); v1 = tanhf(v1); }
                if (mode & 2) { v0 = tf32f(v0); v1 = tf32f(v1); }
                *(float2*)&C[(size_t)r * N + cb] = make_float2(v0, v1);
            }
        }
    }
}

// ---------------- weight/obs conversion + adjacency init ----------------
__global__ void cvt_init(
    const float* __restrict__ obs, const float* __restrict__ embW,
    const float* __restrict__ lowWl, const float* __restrict__ lowWr,
    const float* __restrict__ highWl, const float* __restrict__ highWr,
    const float* __restrict__ W1, const float* __restrict__ W2)
{
    int i = blockIdx.x * blockDim.x + threadIdx.x;
    if (i < NN) g_deg[i] = 0;
    if (i < EHIGH) g_hcols[i] = ((i >> 8) << 4) | (i & 15);
    if (i < NHIGH) g_hdeg[i] = CC;
    int stride = gridDim.x * blockDim.x;
    for (int idx = i; idx < WTOTAL; idx += stride) {
        float v;
        if (idx < EMBW_OFF)        v = obs[idx - OBS_OFF];
        else if (idx < LOWWL_OFF)  v = embW[idx - EMBW_OFF];
        else if (idx < LOWWR_OFF)  v = lowWl[idx - LOWWL_OFF];
        else if (idx < HIGHWL_OFF) v = lowWr[idx - LOWWR_OFF];
        else if (idx < HIGHWR_OFF) v = highWl[idx - HIGHWL_OFF];
        else if (idx < MLPW1_OFF)  v = highWr[idx - HIGHWR_OFF];
        else if (idx < MLPW2_OFF)  v = W1[idx - MLPW1_OFF];
        else                       v = W2[idx - MLPW2_OFF];
        g_wc[idx] = tf32f(v);
    }
}

// ---------------- adjacency ----------------
__global__ void csr_scatter(const int* __restrict__ edge_index)
{
    int i = blockIdx.x * blockDim.x + threadIdx.x;
    if (i >= ETLOW) return;
    int s, d;
    if (i < ELOW) { s = edge_index[i]; d = edge_index[ELOW + i]; }
    else { s = d = i - ELOW; }
    int slot = atomicAdd(&g_deg[d], 1);
    if (slot < CAP) g_cols[d * CAP + slot] = s;
}

// ---------------- fused GAT layer (in-block sort option) ----------------
__global__ __launch_bounds__(128) void fused_gat(
    const float* __restrict__ xl, const float* __restrict__ xr,
    const int* __restrict__ deg, int* __restrict__ cols, int cap,
    const float* __restrict__ att,
    float* __restrict__ h, float* __restrict__ hc,
    const float* __restrict__ bias, const float* __restrict__ g,
    const float* __restrict__ beta, const float* __restrict__ res,
    int do_silu, int do_sort)
{
    int row = blockIdx.x;
    int t = threadIdx.x;
    int w = t >> 5, lane = t & 31;
    int d0 = w * HIDDIM + lane * 4;

    float4 xr4 = *(const float4*)&xr[(size_t)row * FDIM + d0];
    float4 at4 = *(const float4*)&att[d0];
    int* c = &cols[(size_t)row * cap];
    int n = min(deg[row], cap);

    __shared__ int sc[CAP];
    if (w == 0) {
        int v0 = (lane < n)      ? c[lane]      : 0x7fffffff;
        int v1 = (lane + 32 < n) ? c[lane + 32] : 0x7fffffff;
        if (do_sort) {
            int r0 = 0, r1 = 0;
            for (int j = 0; j < n; j++) {
                int vj = __shfl_sync(0xffffffffu, (j < 32) ? v0 : v1, j & 31);
                r0 += (vj < v0) | ((vj == v0) & (j < lane));
                r1 += (vj < v1) | ((vj == v1) & (j < lane + 32));
            }
            __syncwarp();
            if (lane < n)      { sc[r0] = v0; c[r0] = v0; }
            if (lane + 32 < n) { sc[r1] = v1; c[r1] = v1; }
        } else {
            if (lane < n)      sc[lane] = v0;
            if (lane + 32 < n) sc[lane + 32] = v1;
        }
    }
    __syncthreads();

    float z = 0.f;
    float a0 = 0.f, a1 = 0.f, a2 = 0.f, a3 = 0.f;

    float4 x0 = *(const float4*)&xl[(size_t)sc[0] * FDIM + d0];
    float4 x1 = (n > 1) ? *(const float4*)&xl[(size_t)sc[1] * FDIM + d0] : x0;

    for (int e = 0; e < n; e += 2) {
        float4 xn0 = x0, xn1 = x1;
        if (e + 2 < n) xn0 = *(const float4*)&xl[(size_t)sc[e + 2] * FDIM + d0];
        if (e + 3 < n) xn1 = *(const float4*)&xl[(size_t)sc[e + 3] * FDIM + d0];

        float u0, u1, u2, u3;
        u0 = x0.x + xr4.x; u0 = u0 > 0.f ? u0 : NEGSLOPE * u0;
        u1 = x0.y + xr4.y; u1 = u1 > 0.f ? u1 : NEGSLOPE * u1;
        u2 = x0.z + xr4.z; u2 = u2 > 0.f ? u2 : NEGSLOPE * u2;
        u3 = x0.w + xr4.w; u3 = u3 > 0.f ? u3 : NEGSLOPE * u3;
        float da = u0 * at4.x + u1 * at4.y + u2 * at4.z + u3 * at4.w;

        u0 = x1.x + xr4.x; u0 = u0 > 0.f ? u0 : NEGSLOPE * u0;
        u1 = x1.y + xr4.y; u1 = u1 > 0.f ? u1 : NEGSLOPE * u1;
        u2 = x1.z + xr4.z; u2 = u2 > 0.f ? u2 : NEGSLOPE * u2;
        u3 = x1.w + xr4.w; u3 = u3 > 0.f ? u3 : NEGSLOPE * u3;
        float db = u0 * at4.x + u1 * at4.y + u2 * at4.z + u3 * at4.w;

#pragma unroll
        for (int o = 16; o; o >>= 1) {
            da += __shfl_xor_sync(0xffffffffu, da, o);
            db += __shfl_xor_sync(0xffffffffu, db, o);
        }
        float pa = __expf(da);
        float pb = (e + 1 < n) ? __expf(db) : 0.f;
        z += pa + pb;
        a0 += pa * x0.x + pb * x1.x;
        a1 += pa * x0.y + pb * x1.y;
        a2 += pa * x0.z + pb * x1.z;
        a3 += pa * x0.w + pb * x1.w;
        x0 = xn0;
        x1 = xn1;
    }

    __shared__ __align__(16) float sh[4][HIDDIM];
    float inv = 0.25f / z;
    ((float4*)sh[w])[lane] = make_float4(a0 * inv, a1 * inv, a2 * inv, a3 * inv);
    __syncthreads();

    float v = sh[0][t] + sh[1][t] + sh[2][t] + sh[3][t] + bias[t];

    __shared__ float red[4];
    float sum = v;
#pragma unroll
    for (int o = 16; o; o >>= 1) sum += __shfl_xor_sync(0xffffffffu, sum, o);
    if (lane == 0) red[w] = sum;
    __syncthreads();
    float mu = (red[0] + red[1] + red[2] + red[3]) * (1.f / 128.f);
    __syncthreads();
    float dv = v - mu;
    float sq = dv * dv;
#pragma unroll
    for (int o = 16; o; o >>= 1) sq += __shfl_xor_sync(0xffffffffu, sq, o);
    if (lane == 0) red[w] = sq;
    __syncthreads();
    float var = (red[0] + red[1] + red[2] + red[3]) * (1.f / 128.f);
    float y = dv * rsqrtf(var + 1e-5f) * g[t] + beta[t];
    if (do_silu) y = y / (1.f + expf(-y));
    y += h[(size_t)row * HIDDIM + t];
    if (res) y += res[(size_t)row * HIDDIM + t];
    h[(size_t)row * HIDDIM + t] = y;
    if (hc) hc[(size_t)row * HIDDIM + t] = tf32f(y);
}

// ---------------- cluster features + fused pooling softmax ----------------
__global__ __launch_bounds__(128) void hf_stage1(const float* __restrict__ h,
                                                 const float* __restrict__ poolW,
                                                 const float* __restrict__ poolB)
{
    int b = blockIdx.x >> 4, chunk = blockIdx.x & 15;
    int t = threadIdx.x;
    int w = t >> 5, lane = t & 31;
    __shared__ float hs[64][HIDDIM + 1];
    __shared__ float ss[64][CC + 1];
    __shared__ float pw[HIDDIM * CC];
    int n0 = chunk * 64;
    const float* hp0 = h + ((size_t)(b * NNODE + n0)) * HIDDIM;
    for (int n = 0; n < 64; n++)
        hs[n][t] = hp0[(size_t)n * HIDDIM + t];
    for (int i = t; i < HIDDIM * CC; i += 128) pw[i] = poolW[i];
    __syncthreads();

    {
        int cidx = lane & 15;
        float pb = poolB[cidx];
#pragma unroll
        for (int pr = 0; pr < 8; pr++) {
            int node = w * 16 + pr * 2 + (lane >> 4);
            float a = 0.f;
#pragma unroll 8
            for (int d = 0; d < HIDDIM; d++) a += hs[node][d] * pw[d * CC + cidx];
            a += pb;
            float mx = a;
#pragma unroll
            for (int o = 8; o; o >>= 1) mx = fmaxf(mx, __shfl_xor_sync(0xffffffffu, mx, o));
            float e = __expf(a - mx);
            float zz = e;
#pragma unroll
            for (int o = 8; o; o >>= 1) zz += __shfl_xor_sync(0xffffffffu, zz, o);
            float sv = e / zz;
            ss[node][cidx] = sv;
            g_s[((size_t)(b * NNODE + n0 + node)) * CC + cidx] = sv;
        }
    }
    __syncthreads();

    float acc[CC];
#pragma unroll
    for (int c = 0; c < CC; c++) acc[c] = 0.f;
    for (int n = 0; n < 64; n++) {
        float hv = hs[n][t];
#pragma unroll
        for (int c = 0; c < CC; c++) acc[c] += ss[n][c] * hv;
    }
    size_t base = ((size_t)blockIdx.x) * CC * HIDDIM;
#pragma unroll
    for (int c = 0; c < CC; c++) g_hfpart[base + (size_t)c * HIDDIM + t] = acc[c];
    if (t < CC) {
        float cs = 0.f;
        for (int n = 0; n < 64; n++) cs += ss[n][t];
        g_cntpart[blockIdx.x * CC + t] = cs;
    }
}

__global__ void hf_stage2(float* __restrict__ Hf, float* __restrict__ Hfc,
                          float* __restrict__ HfRes)
{
    int bc = blockIdx.x;
    int b = bc >> 4, c = bc & 15;
    int t = threadIdx.x;
    float acc = 0.f, cnt = 0.f;
#pragma unroll
    for (int ch = 0; ch < HFCH; ch++) {
        acc += g_hfpart[(((size_t)(b * HFCH + ch)) * CC + c) * HIDDIM + t];
        cnt += g_cntpart[(b * HFCH + ch) * CC + c];
    }
    float v = acc / fmaxf(cnt, 1e-5f);
    Hf[(size_t)bc * HIDDIM + t] = v;
    Hfc[(size_t)bc * HIDDIM + t] = tf32f(v);
    HfRes[(size_t)bc * HIDDIM + t] = v;
}

// x = hh + s @ Hf; tf32 copy for MLP1
__global__ void unpool_kernel(const float* __restrict__ s, const float* __restrict__ Hf,
                              const float* __restrict__ hh,
                              float* __restrict__ x, float* __restrict__ xc)
{
    int idx = blockIdx.x * blockDim.x + threadIdx.x;
    if (idx >= NN * HIDDIM) return;
    int n = idx >> 7, t = idx & 127;
    int b = n >> 10;
    float v = hh[idx];
    const float* sp = s + (size_t)n * CC;
    const float* Hp = Hf + (size_t)(b * CC) * HIDDIM + t;
#pragma unroll
    for (int c = 0; c < CC; c++) v += sp[c] * Hp[(size_t)c * HIDDIM];
    x[idx] = v;
    xc[idx] = tf32f(v);
}

// ---------------- host orchestration ----------------
struct Ptrs {
    float *h, *hc, *hh, *xl, *xr, *s, *Hf, *Hfc, *HfRes, *x, *xc, *wc;
    int *deg, *cols, *hdeg, *hcols;
};

static void get_ptrs(Ptrs& P)
{
    cudaGetSymbolAddress((void**)&P.h, g_h);
    cudaGetSymbolAddress((void**)&P.hc, g_hc);
    cudaGetSymbolAddress((void**)&P.hh, g_hh);
    cudaGetSymbolAddress((void**)&P.xl, g_xl);
    cudaGetSymbolAddress((void**)&P.xr, g_xr);
    cudaGetSymbolAddress((void**)&P.s, g_s);
    cudaGetSymbolAddress((void**)&P.Hf, g_Hf);
    cudaGetSymbolAddress((void**)&P.Hfc, g_Hfc);
    cudaGetSymbolAddress((void**)&P.HfRes, g_HfRes);
    cudaGetSymbolAddress((void**)&P.x, g_x);
    cudaGetSymbolAddress((void**)&P.xc, g_xc);
    cudaGetSymbolAddress((void**)&P.wc, g_wc);
    cudaGetSymbolAddress((void**)&P.deg, g_deg);
    cudaGetSymbolAddress((void**)&P.cols, g_cols);
    cudaGetSymbolAddress((void**)&P.hdeg, g_hdeg);
    cudaGetSymbolAddress((void**)&P.hcols, g_hcols);
}

extern "C" void kernel_launch(void* const* d_in, const int* in_sizes, int n_in,
                              void* d_out, int out_size)
{
    int p = 0;
    const float* obs        = (const float*)d_in[p++];
    const int*   edge_index = (const int*)d_in[p++];
    if (n_in >= 27) p++;  // skip n_node scalar if present
    const float* emb_W   = (const float*)d_in[p++];
    const float* emb_b   = (const float*)d_in[p++];
    const float* pool_W  = (const float*)d_in[p++];
    const float* pool_b  = (const float*)d_in[p++];
    const float* mlp_W1  = (const float*)d_in[p++];
    const float* mlp_b1  = (const float*)d_in[p++];
    const float* mlp_W2  = (const float*)d_in[p++];
    const float* mlp_b2  = (const float*)d_in[p++];
    const float* low_Wl   = (const float*)d_in[p++];
    const float* low_bl   = (const float*)d_in[p++];
    const float* low_Wr   = (const float*)d_in[p++];
    const float* low_br   = (const float*)d_in[p++];
    const float* low_att  = (const float*)d_in[p++];
    const float* low_bias = (const float*)d_in[p++];
    const float* low_g    = (const float*)d_in[p++];
    const float* low_beta = (const float*)d_in[p++];
    const float* high_Wl   = (const float*)d_in[p++];
    const float* high_bl   = (const float*)d_in[p++];
    const float* high_Wr   = (const float*)d_in[p++];
    const float* high_br   = (const float*)d_in[p++];
    const float* high_att  = (const float*)d_in[p++];
    const float* high_bias = (const float*)d_in[p++];
    const float* high_g    = (const float*)d_in[p++];
    const float* high_beta = (const float*)d_in[p++];

    Ptrs P;
    get_ptrs(P);
    float* out = (float*)d_out;

    // 1. weight/obs tf32 conversion + adjacency init
    cvt_init<<<1024, 256>>>(obs, emb_W, low_Wl, low_Wr, high_Wl, high_Wr,
                            mlp_W1, mlp_W2);
    // 2. embed
    gemm64_kernel<<<dim3(2, NN / 128), 128>>>(P.wc + OBS_OFF, P.wc + EMBW_OFF, emb_b,
                                              P.h, P.hh, P.hc, nullptr,
                                              HIDDIM, 32, 0);
    // 3. edge scatter
    csr_scatter<<<(ETLOW + 255) / 256, 256>>>(edge_index);
    // 4. low layer 0 transforms  <- profiled slot
    dual_gemm64_kernel<<<dim3(16, NN / 128), 128>>>(
        P.hc, P.wc + LOWWL_OFF, low_bl, P.xl,
        P.wc + LOWWR_OFF, low_br, P.xr, HIDDIM);
    // 5. low layer 0 attention (sorts adjacency in-block, writes back)
    fused_gat<<<NN, 128>>>(P.xl, P.xr, P.deg, P.cols, CAP, low_att, P.h, P.hc,
                           low_bias, low_g, low_beta, nullptr, 1, 1);
    // 6-7. low layer 1
    dual_gemm64_kernel<<<dim3(16, NN / 128), 128>>>(
        P.hc, P.wc + LOWWL_OFF + 65536, low_bl + FDIM, P.xl,
        P.wc + LOWWR_OFF + 65536, low_br + FDIM, P.xr, HIDDIM);
    fused_gat<<<NN, 128>>>(P.xl, P.xr, P.deg, P.cols, CAP, low_att + FDIM, P.h, nullptr,
                           low_bias + HIDDIM, low_g + HIDDIM, low_beta + HIDDIM,
                           P.hh, 0, 0);

    // 8-9. cluster features (+ fused pooling softmax in stage1)
    hf_stage1<<<BBATCH * HFCH, 128>>>(P.h, pool_W, pool_b);
    hf_stage2<<<NHIGH, HIDDIM>>>(P.Hf, P.Hfc, P.HfRes);

    // 10-13. high-level GAT stack
    dual_gemm64_kernel<<<dim3(16, NHIGH / 128), 128>>>(
        P.Hfc, P.wc + HIGHWL_OFF, high_bl, P.xl,
        P.wc + HIGHWR_OFF, high_br, P.xr, HIDDIM);
    fused_gat<<<NHIGH, 128>>>(P.xl, P.xr, P.hdeg, P.hcols, CC, high_att,
                              P.Hf, P.Hfc, high_bias, high_g, high_beta, nullptr, 1, 0);
    dual_gemm64_kernel<<<dim3(16, NHIGH / 128), 128>>>(
        P.Hfc, P.wc + HIGHWL_OFF + 65536, high_bl + FDIM, P.xl,
        P.wc + HIGHWR_OFF + 65536, high_br + FDIM, P.xr, HIDDIM);
    fused_gat<<<NHIGH, 128>>>(P.xl, P.xr, P.hdeg, P.hcols, CC, high_att + FDIM,
                              P.Hf, nullptr, high_bias + HIDDIM, high_g + HIDDIM,
                              high_beta + HIDDIM, P.HfRes, 0, 0);

    // 14. unpool + residual
    unpool_kernel<<<(NN * HIDDIM + 255) / 256, 256>>>(P.s, P.Hf, P.hh, P.x, P.xc);

    // 15-16. MLP (MLP1 on 128-wide tiles: A read 4x instead of 8x)
    tgemm128_kernel<<<dim3(4, NN / 128), 256>>>(P.xc, P.wc + MLPW1_OFF, mlp_b1, P.xl,
                                                FDIM, HIDDIM, 3);
    gemm64_kernel<<<dim3(2, NN / 128), 128>>>(P.xl, P.wc + MLPW2_OFF, mlp_b2, out,
                                              nullptr, nullptr, P.x,
                                              HIDDIM, FDIM, 0);
}